// round 1
// baseline (speedup 1.0000x reference)
#include <cuda_runtime.h>
#include <cuda_bf16.h>
#include <cstdint>

// Problem constants
#define M_ROWS   16425
#define M_PAD    16512            // multiple of 128
#define HID      2048
#define K_LEV    5
#define BAND     8

// GEMM tiling
#define BM 128
#define BN 128
#define BK 32
#define NT (HID / BK)             // 64 k-tiles
#define AS_STRIDE 36              // 32 + 4 pad (conflict-free fragment loads)
#define BS_STRIDE 132             // 128 + 4 pad
#define AS_FLOATS (BM * AS_STRIDE)      // 4608
#define BS_FLOATS (BK * BS_STRIDE)      // 4224
#define STAGE_FLOATS (AS_FLOATS + BS_FLOATS)   // 8832
#define SMEM_BYTES (STAGE_FLOATS * 2 * 4)      // 70656

// ---------------------------------------------------------------------------
// Scratch (static device allocations — no cudaMalloc allowed)
// ---------------------------------------------------------------------------
__device__ float g_h0[(size_t)M_PAD * HID];
__device__ float g_h1[(size_t)M_PAD * HID];
__device__ float g_amg[16448];
__device__ float g_mg0[262145];
__device__ float g_mg1[262145];

// ---------------------------------------------------------------------------
// PTX helpers
// ---------------------------------------------------------------------------
__device__ __forceinline__ void cp_async16(void* smem, const void* gmem) {
    uint32_t s = (uint32_t)__cvta_generic_to_shared(smem);
    asm volatile("cp.async.cg.shared.global [%0], [%1], 16;\n" :: "r"(s), "l"(gmem));
}
__device__ __forceinline__ void cp_commit() {
    asm volatile("cp.async.commit_group;\n" ::);
}
__device__ __forceinline__ uint32_t f2tf32(float f) {
    uint32_t r;
    asm("cvt.rna.tf32.f32 %0, %1;\n" : "=r"(r) : "f"(f));
    return r;
}
__device__ __forceinline__ void mma_tf32(float* d, const uint32_t* a, const uint32_t* b) {
    asm volatile(
        "mma.sync.aligned.m16n8k8.row.col.f32.tf32.tf32.f32 "
        "{%0,%1,%2,%3}, {%4,%5,%6,%7}, {%8,%9}, {%0,%1,%2,%3};\n"
        : "+f"(d[0]), "+f"(d[1]), "+f"(d[2]), "+f"(d[3])
        : "r"(a[0]), "r"(a[1]), "r"(a[2]), "r"(a[3]), "r"(b[0]), "r"(b[1]));
}

// ---------------------------------------------------------------------------
// Layer 0:  h0[i][j] = relu(xs[i]*w0[j] + b0[j]),  pad rows -> 0
// ---------------------------------------------------------------------------
__global__ void layer0_kernel(const float* __restrict__ xs,
                              const float* __restrict__ w0,
                              const float* __restrict__ b0) {
    int idx = blockIdx.x * blockDim.x + threadIdx.x;
    if (idx >= M_PAD * HID) return;
    int i = idx >> 11;
    int j = idx & (HID - 1);
    float v = 0.0f;
    if (i < M_ROWS) v = fmaxf(fmaf(xs[i], w0[j], b0[j]), 0.0f);
    g_h0[idx] = v;
}

// ---------------------------------------------------------------------------
// Fused GEMM + bias + ReLU:  C = relu(A @ W + b)
// A: [M_PAD, 2048] (g_h0/g_h1), W: [2048, 2048] row-major, C: [M_PAD, 2048]
// sel==0: A=g_h0, C=g_h1 ; sel==1: A=g_h1, C=g_h0
// ---------------------------------------------------------------------------
__global__ void __launch_bounds__(256, 2)
gemm_relu_kernel(const float* __restrict__ W,
                 const float* __restrict__ bias,
                 int sel) {
    const float* __restrict__ A = sel ? g_h1 : g_h0;
    float* __restrict__ C       = sel ? g_h0 : g_h1;

    extern __shared__ float sm[];

    const int t    = threadIdx.x;
    const int lane = t & 31;
    const int wid  = t >> 5;
    const int wm   = wid & 1;     // 0..1  -> 64-row slab
    const int wn   = wid >> 1;    // 0..3  -> 32-col slab
    const int g    = lane >> 2;   // 0..7
    const int tg   = lane & 3;    // 0..3

    const int bm = blockIdx.y * BM;
    const int bn = blockIdx.x * BN;

    // global load coords
    const int ar = t >> 3;          // 0..31
    const int ac = (t & 7) * 4;     // 0..28
    const int br = t >> 5;          // 0..7
    const int bc = (t & 31) * 4;    // 0..124

    float acc[4][4][4];
#pragma unroll
    for (int i = 0; i < 4; i++)
#pragma unroll
        for (int j = 0; j < 4; j++)
#pragma unroll
            for (int r = 0; r < 4; r++) acc[i][j][r] = 0.0f;

    auto load_tile = [&](int kt, int stage) {
        float* As = sm + stage * STAGE_FLOATS;
        float* Bs = As + AS_FLOATS;
        const int k0 = kt * BK;
#pragma unroll
        for (int it = 0; it < 4; it++) {
            int row = ar + it * 32;
            cp_async16(&As[row * AS_STRIDE + ac],
                       A + (size_t)(bm + row) * HID + k0 + ac);
        }
#pragma unroll
        for (int it = 0; it < 4; it++) {
            int row = br + it * 8;
            cp_async16(&Bs[row * BS_STRIDE + bc],
                       W + (size_t)(k0 + row) * HID + bn + bc);
        }
        cp_commit();
    };

    load_tile(0, 0);

#pragma unroll 1
    for (int kt = 0; kt < NT; kt++) {
        if (kt + 1 < NT) {
            load_tile(kt + 1, (kt + 1) & 1);
            asm volatile("cp.async.wait_group 1;\n" ::);
        } else {
            asm volatile("cp.async.wait_group 0;\n" ::);
        }
        __syncthreads();

        const float* As = sm + (kt & 1) * STAGE_FLOATS;
        const float* Bs = As + AS_FLOATS;

#pragma unroll
        for (int kk = 0; kk < 4; kk++) {
            const int kb = kk * 8;
            uint32_t af[4][4];
            uint32_t bf[4][2];
#pragma unroll
            for (int tm = 0; tm < 4; tm++) {
                int r = wm * 64 + tm * 16 + g;
                af[tm][0] = f2tf32(As[r * AS_STRIDE + kb + tg]);
                af[tm][1] = f2tf32(As[(r + 8) * AS_STRIDE + kb + tg]);
                af[tm][2] = f2tf32(As[r * AS_STRIDE + kb + tg + 4]);
                af[tm][3] = f2tf32(As[(r + 8) * AS_STRIDE + kb + tg + 4]);
            }
#pragma unroll
            for (int tn = 0; tn < 4; tn++) {
                int c = wn * 32 + tn * 8 + g;
                bf[tn][0] = f2tf32(Bs[(kb + tg) * BS_STRIDE + c]);
                bf[tn][1] = f2tf32(Bs[(kb + tg + 4) * BS_STRIDE + c]);
            }
#pragma unroll
            for (int tm = 0; tm < 4; tm++)
#pragma unroll
                for (int tn = 0; tn < 4; tn++)
                    mma_tf32(acc[tm][tn], af[tm], bf[tn]);
        }
        __syncthreads();
    }

    // Epilogue: bias + relu, store (pad rows are in-bounds of padded buffers)
#pragma unroll
    for (int tn = 0; tn < 4; tn++) {
        int c0 = bn + wn * 32 + tn * 8 + 2 * tg;
        float bv0 = bias[c0];
        float bv1 = bias[c0 + 1];
#pragma unroll
        for (int tm = 0; tm < 4; tm++) {
            int r0 = bm + wm * 64 + tm * 16 + g;
            float* Cr0 = C + (size_t)r0 * HID + c0;
            float* Cr1 = C + (size_t)(r0 + 8) * HID + c0;
            Cr0[0] = fmaxf(acc[tm][tn][0] + bv0, 0.0f);
            Cr0[1] = fmaxf(acc[tm][tn][1] + bv1, 0.0f);
            Cr1[0] = fmaxf(acc[tm][tn][2] + bv0, 0.0f);
            Cr1[1] = fmaxf(acc[tm][tn][3] + bv1, 0.0f);
        }
    }
}

// ---------------------------------------------------------------------------
// Final layer GEMV: Amg[i] = relu(dot(h[i,:], w4) + b4)   (reads g_h1)
// ---------------------------------------------------------------------------
__global__ void gemv_kernel(const float* __restrict__ w4,
                            const float* __restrict__ b4) {
    int warp = (blockIdx.x * blockDim.x + threadIdx.x) >> 5;
    int lane = threadIdx.x & 31;
    if (warp >= M_ROWS) return;
    const float4* hv = (const float4*)(g_h1 + (size_t)warp * HID);
    const float4* wv = (const float4*)w4;
    float s = 0.0f;
#pragma unroll
    for (int i = lane; i < HID / 4; i += 32) {
        float4 a = hv[i];
        float4 b = wv[i];
        s += a.x * b.x + a.y * b.y + a.z * b.z + a.w * b.w;
    }
#pragma unroll
    for (int off = 16; off > 0; off >>= 1)
        s += __shfl_xor_sync(0xFFFFFFFFu, s, off);
    if (lane == 0) g_amg[warp] = fmaxf(s + b4[0], 0.0f);
}

// ---------------------------------------------------------------------------
// Multigrid level: interp (2n-1) + inline scatter of the 8 band values.
// All nbrs indices are odd (interpolated positions), so scatter fuses safely.
// ---------------------------------------------------------------------------
__global__ void mg_kernel(int lvl, const int* __restrict__ nbrs, float* dout) {
    const float* in;
    float* out;
    switch (lvl) {
        case 0: in = g_amg + 40; out = g_mg0; break;
        case 1: in = g_mg0;      out = g_mg1; break;
        case 2: in = g_mg1;      out = g_mg0; break;
        case 3: in = g_mg0;      out = g_mg1; break;
        default: in = g_mg1;     out = dout;  break;
    }
    const int n_in  = (16384 << lvl) + 1;
    const int n_out = 2 * n_in - 1;
    const int* nbr8 = nbrs + lvl * 8;
    const float* band = g_amg + 8 * (4 - lvl);

    int p = blockIdx.x * blockDim.x + threadIdx.x;
    if (p >= n_out) return;
    float v;
    if (p & 1) {
        int h = p >> 1;
        v = 0.5f * (in[h] + in[h + 1]);
#pragma unroll
        for (int j = 0; j < 8; j++)
            if (p == nbr8[j]) v = band[j];
    } else {
        v = in[p >> 1];
    }
    out[p] = v;
}

// ---------------------------------------------------------------------------
// Launch
// ---------------------------------------------------------------------------
extern "C" void kernel_launch(void* const* d_in, const int* in_sizes, int n_in,
                              void* d_out, int out_size) {
    const float *xs, *w0, *b0, *w1, *b1, *w2, *b2, *w3, *b3, *w4, *b4;
    const int* nbrs;

    if (n_in >= 2 && in_sizes[1] == 40) {
        // setup_inputs dict order: xs, nbrs, k, m, w0, b0, w1, b1, ...
        xs   = (const float*)d_in[0];
        nbrs = (const int*)d_in[1];
        w0 = (const float*)d_in[4];  b0 = (const float*)d_in[5];
        w1 = (const float*)d_in[6];  b1 = (const float*)d_in[7];
        w2 = (const float*)d_in[8];  b2 = (const float*)d_in[9];
        w3 = (const float*)d_in[10]; b3 = (const float*)d_in[11];
        w4 = (const float*)d_in[12]; b4 = (const float*)d_in[13];
    } else {
        // reference signature order: xs, w0, b0, ..., w4, b4, nbrs, k, m
        xs   = (const float*)d_in[0];
        w0 = (const float*)d_in[1];  b0 = (const float*)d_in[2];
        w1 = (const float*)d_in[3];  b1 = (const float*)d_in[4];
        w2 = (const float*)d_in[5];  b2 = (const float*)d_in[6];
        w3 = (const float*)d_in[7];  b3 = (const float*)d_in[8];
        w4 = (const float*)d_in[9];  b4 = (const float*)d_in[10];
        nbrs = (const int*)d_in[11];
    }

    cudaFuncSetAttribute(gemm_relu_kernel,
                         cudaFuncAttributeMaxDynamicSharedMemorySize, SMEM_BYTES);

    // Layer 0
    {
        int total = M_PAD * HID;
        layer0_kernel<<<(total + 255) / 256, 256>>>(xs, w0, b0);
    }

    // Three hidden GEMMs (fused bias + relu)
    dim3 grid(HID / BN, M_PAD / BM);  // (16, 129)
    gemm_relu_kernel<<<grid, 256, SMEM_BYTES>>>(w1, b1, 0); // h0 -> h1
    gemm_relu_kernel<<<grid, 256, SMEM_BYTES>>>(w2, b2, 1); // h1 -> h0
    gemm_relu_kernel<<<grid, 256, SMEM_BYTES>>>(w3, b3, 0); // h0 -> h1

    // Final GEMV -> g_amg
    {
        int warps_needed = M_ROWS;
        int blocks = (warps_needed * 32 + 255) / 256;
        gemv_kernel<<<blocks, 256>>>(w4, b4);
    }

    // Multigrid reconstruction, last level writes d_out
    for (int lvl = 0; lvl < K_LEV; lvl++) {
        int n_out_l = (16384 << (lvl + 1)) + 1;
        int blocks = (n_out_l + 255) / 256;
        mg_kernel<<<blocks, 256>>>(lvl, nbrs, (float*)d_out);
    }
    (void)out_size;
}

// round 3
// speedup vs baseline: 1.1534x; 1.1534x over previous
#include <cuda_runtime.h>
#include <cuda_bf16.h>
#include <cstdint>

// Problem constants
#define M_ROWS   16425
#define M_PAD    16512            // 129 * 128
#define HID      2048
#define K_LEV    5

// GEMM tiling: 128x128 CTA tile, 4 warps of 64x64, BK=32, 3-stage cp.async
#define BM 128
#define BN 128
#define BK 32
#define NT (HID / BK)             // 64
#define NSTAGE 3
#define AS_STRIDE 36              // 32 + 4 pad  -> A frag banks = lane (conflict-free)
#define BS_STRIDE 136             // 128 + 8 pad -> B frag banks = 8*tg+g (conflict-free)
#define AS_FLOATS (BM * AS_STRIDE)             // 4608
#define BS_FLOATS (BK * BS_STRIDE)             // 4352
#define STAGE_FLOATS (AS_FLOATS + BS_FLOATS)   // 8960
#define SMEM_BYTES (STAGE_FLOATS * NSTAGE * 4) // 107520

// ---------------------------------------------------------------------------
// Static device scratch
// ---------------------------------------------------------------------------
__device__ float g_h0[(size_t)M_PAD * HID];
__device__ float g_h1[(size_t)M_PAD * HID];
__device__ float g_wr[3][(size_t)HID * HID];   // tf32-pre-rounded weights
__device__ float g_amg[16448];
__device__ float g_mg0[262145];
__device__ float g_mg1[262145];

// ---------------------------------------------------------------------------
// PTX helpers
// ---------------------------------------------------------------------------
__device__ __forceinline__ void cp_async16(void* smem, const void* gmem) {
    uint32_t s = (uint32_t)__cvta_generic_to_shared(smem);
    asm volatile("cp.async.cg.shared.global [%0], [%1], 16;\n" :: "r"(s), "l"(gmem));
}
__device__ __forceinline__ void cp_commit() {
    asm volatile("cp.async.commit_group;\n" ::);
}
__device__ __forceinline__ uint32_t f2tf32(float f) {
    uint32_t r;
    asm("cvt.rna.tf32.f32 %0, %1;\n" : "=r"(r) : "f"(f));
    return r;
}
// Operands are pre-rounded tf32 bit patterns living in f32 storage.
__device__ __forceinline__ void mma_tf32(float* d, const uint32_t* a, const uint32_t* b) {
    asm volatile(
        "mma.sync.aligned.m16n8k8.row.col.f32.tf32.tf32.f32 "
        "{%0,%1,%2,%3}, {%4,%5,%6,%7}, {%8,%9}, {%0,%1,%2,%3};\n"
        : "+f"(d[0]), "+f"(d[1]), "+f"(d[2]), "+f"(d[3])
        : "r"(a[0]), "r"(a[1]), "r"(a[2]), "r"(a[3]), "r"(b[0]), "r"(b[1]));
}

// ---------------------------------------------------------------------------
// Weight pre-round:  out[i] = rna(in[i])
// ---------------------------------------------------------------------------
__global__ void round_weights(const float* __restrict__ in, float* __restrict__ out) {
    int i = blockIdx.x * blockDim.x + threadIdx.x;
    if (i < HID * HID) out[i] = __uint_as_float(f2tf32(in[i]));
}

// ---------------------------------------------------------------------------
// Layer 0:  h0[i][j] = rna(relu(xs[i]*w0[j] + b0[j])),  pad rows -> 0
// ---------------------------------------------------------------------------
__global__ void layer0_kernel(const float* __restrict__ xs,
                              const float* __restrict__ w0,
                              const float* __restrict__ b0) {
    int idx = blockIdx.x * blockDim.x + threadIdx.x;
    if (idx >= M_PAD * HID) return;
    int i = idx >> 11;
    int j = idx & (HID - 1);
    float v = 0.0f;
    if (i < M_ROWS)
        v = __uint_as_float(f2tf32(fmaxf(fmaf(xs[i], w0[j], b0[j]), 0.0f)));
    g_h0[idx] = v;
}

// ---------------------------------------------------------------------------
// Fused GEMM + bias + ReLU (+optional tf32 round of output)
// C = act(A @ W + b).  A,C: [M_PAD,2048] row-major. W: [2048,2048] row-major,
// consumed as col-major B (k rows x n cols per tile).
// sel==0: A=g_h0, C=g_h1 ; sel==1: A=g_h1, C=g_h0
// ---------------------------------------------------------------------------
__global__ void __launch_bounds__(128, 2)
gemm_relu_kernel(const float* __restrict__ W,
                 const float* __restrict__ bias,
                 int sel, int round_out) {
    const float* __restrict__ A = sel ? g_h1 : g_h0;
    float* __restrict__ C       = sel ? g_h0 : g_h1;

    extern __shared__ float sm[];

    const int t    = threadIdx.x;
    const int lane = t & 31;
    const int wid  = t >> 5;
    const int wm   = wid & 1;     // 0..1 -> 64-row slab
    const int wn   = wid >> 1;    // 0..1 -> 64-col slab
    const int g    = lane >> 2;   // 0..7
    const int tg   = lane & 3;    // 0..3

    const int bm = blockIdx.y * BM;
    const int bn = blockIdx.x * BN;

    // global->smem coords (128 threads)
    const int ar = t >> 3;          // 0..15
    const int ac = (t & 7) * 4;     // 0..28
    const int br = t >> 5;          // 0..3
    const int bc = (t & 31) * 4;    // 0..124

    float acc[4][8][4];
#pragma unroll
    for (int i = 0; i < 4; i++)
#pragma unroll
        for (int j = 0; j < 8; j++)
#pragma unroll
            for (int r = 0; r < 4; r++) acc[i][j][r] = 0.0f;

    auto load_tile = [&](int kt, int stage) {
        float* As = sm + stage * STAGE_FLOATS;
        float* Bs = As + AS_FLOATS;
        const int k0 = kt * BK;
#pragma unroll
        for (int it = 0; it < 8; it++) {
            int row = ar + it * 16;
            cp_async16(&As[row * AS_STRIDE + ac],
                       A + (size_t)(bm + row) * HID + k0 + ac);
        }
#pragma unroll
        for (int it = 0; it < 8; it++) {
            int row = br + it * 4;
            cp_async16(&Bs[row * BS_STRIDE + bc],
                       W + (size_t)(k0 + row) * HID + bn + bc);
        }
        cp_commit();
    };

    load_tile(0, 0);
    load_tile(1, 1);
    asm volatile("cp.async.wait_group 1;\n" ::);
    __syncthreads();

#pragma unroll 1
    for (int kt = 0; kt < NT; kt++) {
        const float* As = sm + (kt % NSTAGE) * STAGE_FLOATS;
        const float* Bs = As + AS_FLOATS;
        const float* aptr = As + (wm * 64 + g) * AS_STRIDE + tg;
        const float* bptr = Bs + tg * BS_STRIDE + wn * 64 + g;

#pragma unroll
        for (int kk = 0; kk < 4; kk++) {
            const int kb = kk * 8;
            uint32_t af[4][4];
            uint32_t bf[8][2];
#pragma unroll
            for (int tm = 0; tm < 4; tm++) {
                af[tm][0] = __float_as_uint(aptr[(tm * 16) * AS_STRIDE + kb]);
                af[tm][1] = __float_as_uint(aptr[(tm * 16 + 8) * AS_STRIDE + kb]);
                af[tm][2] = __float_as_uint(aptr[(tm * 16) * AS_STRIDE + kb + 4]);
                af[tm][3] = __float_as_uint(aptr[(tm * 16 + 8) * AS_STRIDE + kb + 4]);
            }
#pragma unroll
            for (int tn = 0; tn < 8; tn++) {
                bf[tn][0] = __float_as_uint(bptr[kb * BS_STRIDE + tn * 8]);
                bf[tn][1] = __float_as_uint(bptr[(kb + 4) * BS_STRIDE + tn * 8]);
            }
#pragma unroll
            for (int tm = 0; tm < 4; tm++)
#pragma unroll
                for (int tn = 0; tn < 8; tn++)
                    mma_tf32(acc[tm][tn], af[tm], bf[tn]);
        }
        __syncthreads();

        // prefetch kt+2 into the stage just freed
        if (kt + 2 < NT) {
            load_tile(kt + 2, (kt + 2) % NSTAGE);
            asm volatile("cp.async.wait_group 1;\n" ::);
        } else if (kt + 2 == NT) {
            asm volatile("cp.async.wait_group 0;\n" ::);
        }
        __syncthreads();
    }

    // Epilogue: bias + relu (+ round), store
#pragma unroll
    for (int tn = 0; tn < 8; tn++) {
        int c0 = bn + wn * 64 + tn * 8 + 2 * tg;
        float bv0 = __ldg(&bias[c0]);
        float bv1 = __ldg(&bias[c0 + 1]);
#pragma unroll
        for (int tm = 0; tm < 4; tm++) {
            int r0 = bm + wm * 64 + tm * 16 + g;
            float* Cr0 = C + (size_t)r0 * HID + c0;
            float* Cr1 = C + (size_t)(r0 + 8) * HID + c0;
            float v00 = fmaxf(acc[tm][tn][0] + bv0, 0.0f);
            float v01 = fmaxf(acc[tm][tn][1] + bv1, 0.0f);
            float v10 = fmaxf(acc[tm][tn][2] + bv0, 0.0f);
            float v11 = fmaxf(acc[tm][tn][3] + bv1, 0.0f);
            if (round_out) {
                v00 = __uint_as_float(f2tf32(v00));
                v01 = __uint_as_float(f2tf32(v01));
                v10 = __uint_as_float(f2tf32(v10));
                v11 = __uint_as_float(f2tf32(v11));
            }
            Cr0[0] = v00; Cr0[1] = v01;
            Cr1[0] = v10; Cr1[1] = v11;
        }
    }
}

// ---------------------------------------------------------------------------
// Final layer GEMV: Amg[i] = relu(dot(h1[i,:], w4) + b4)
// ---------------------------------------------------------------------------
__global__ void gemv_kernel(const float* __restrict__ w4,
                            const float* __restrict__ b4) {
    int warp = (blockIdx.x * blockDim.x + threadIdx.x) >> 5;
    int lane = threadIdx.x & 31;
    if (warp >= M_ROWS) return;
    const float4* hv = (const float4*)(g_h1 + (size_t)warp * HID);
    const float4* wv = (const float4*)w4;
    float s = 0.0f;
#pragma unroll
    for (int i = lane; i < HID / 4; i += 32) {
        float4 a = hv[i];
        float4 b = wv[i];
        s += a.x * b.x + a.y * b.y + a.z * b.z + a.w * b.w;
    }
#pragma unroll
    for (int off = 16; off > 0; off >>= 1)
        s += __shfl_xor_sync(0xFFFFFFFFu, s, off);
    if (lane == 0) g_amg[warp] = fmaxf(s + b4[0], 0.0f);
}

// ---------------------------------------------------------------------------
// Multigrid level: interp (2n-1) + inline scatter of the 8 band values.
// ---------------------------------------------------------------------------
__global__ void mg_kernel(int lvl, const int* __restrict__ nbrs, float* dout) {
    const float* in;
    float* out;
    switch (lvl) {
        case 0: in = g_amg + 40; out = g_mg0; break;
        case 1: in = g_mg0;      out = g_mg1; break;
        case 2: in = g_mg1;      out = g_mg0; break;
        case 3: in = g_mg0;      out = g_mg1; break;
        default: in = g_mg1;     out = dout;  break;
    }
    const int n_out = 2 * ((16384 << lvl) + 1) - 1;
    const int* nbr8 = nbrs + lvl * 8;
    const float* band = g_amg + 8 * (4 - lvl);

    int p = blockIdx.x * blockDim.x + threadIdx.x;
    if (p >= n_out) return;
    float v;
    if (p & 1) {
        int h = p >> 1;
        v = 0.5f * (in[h] + in[h + 1]);
#pragma unroll
        for (int j = 0; j < 8; j++)
            if (p == nbr8[j]) v = band[j];
    } else {
        v = in[p >> 1];
    }
    out[p] = v;
}

// ---------------------------------------------------------------------------
// Launch
// ---------------------------------------------------------------------------
extern "C" void kernel_launch(void* const* d_in, const int* in_sizes, int n_in,
                              void* d_out, int out_size) {
    const float *xs, *w0, *b0, *w1, *b1, *w2, *b2, *w3, *b3, *w4, *b4;
    const int* nbrs;

    if (n_in >= 2 && in_sizes[1] == 40) {
        xs   = (const float*)d_in[0];
        nbrs = (const int*)d_in[1];
        w0 = (const float*)d_in[4];  b0 = (const float*)d_in[5];
        w1 = (const float*)d_in[6];  b1 = (const float*)d_in[7];
        w2 = (const float*)d_in[8];  b2 = (const float*)d_in[9];
        w3 = (const float*)d_in[10]; b3 = (const float*)d_in[11];
        w4 = (const float*)d_in[12]; b4 = (const float*)d_in[13];
    } else {
        xs   = (const float*)d_in[0];
        w0 = (const float*)d_in[1];  b0 = (const float*)d_in[2];
        w1 = (const float*)d_in[3];  b1 = (const float*)d_in[4];
        w2 = (const float*)d_in[5];  b2 = (const float*)d_in[6];
        w3 = (const float*)d_in[7];  b3 = (const float*)d_in[8];
        w4 = (const float*)d_in[9];  b4 = (const float*)d_in[10];
        nbrs = (const int*)d_in[11];
    }

    void* p_wr;
    cudaGetSymbolAddress(&p_wr, g_wr);
    float* wr0 = (float*)p_wr;
    float* wr1 = wr0 + (size_t)HID * HID;
    float* wr2 = wr1 + (size_t)HID * HID;

    cudaFuncSetAttribute(gemm_relu_kernel,
                         cudaFuncAttributeMaxDynamicSharedMemorySize, SMEM_BYTES);

    // Pre-round weights to tf32 (one elementwise pass each)
    {
        int total = HID * HID;
        int blk = (total + 255) / 256;
        round_weights<<<blk, 256>>>(w1, wr0);
        round_weights<<<blk, 256>>>(w2, wr1);
        round_weights<<<blk, 256>>>(w3, wr2);
    }

    // Layer 0 (rounds its output)
    layer0_kernel<<<(M_PAD * HID + 255) / 256, 256>>>(xs, w0, b0);

    // Three hidden GEMMs; first two round outputs (consumed by tf32 mma),
    // third leaves fp32 for the GEMV — numerics identical to Round 1.
    dim3 grid(HID / BN, M_PAD / BM);  // (16, 129)
    gemm_relu_kernel<<<grid, 128, SMEM_BYTES>>>(wr0, b1, 0, 1); // h0 -> h1
    gemm_relu_kernel<<<grid, 128, SMEM_BYTES>>>(wr1, b2, 1, 1); // h1 -> h0
    gemm_relu_kernel<<<grid, 128, SMEM_BYTES>>>(wr2, b3, 0, 0); // h0 -> h1

    // Final GEMV -> g_amg
    gemv_kernel<<<(M_ROWS * 32 + 255) / 256, 256>>>(w4, b4);

    // Multigrid reconstruction
    for (int lvl = 0; lvl < K_LEV; lvl++) {
        int n_out_l = (16384 << (lvl + 1)) + 1;
        mg_kernel<<<(n_out_l + 255) / 256, 256>>>(lvl, nbrs, (float*)d_out);
    }
    (void)out_size;
}

// round 4
// speedup vs baseline: 1.9563x; 1.6962x over previous
#include <cuda_runtime.h>
#include <cuda_fp16.h>
#include <cstdint>

// Problem constants
#define M_ROWS   16425
#define M_PAD    16512            // 129 * 128
#define HID      2048
#define K_LEV    5

// GEMM tiling: CTA 128x256, 8 warps of 64x64, BK=32 (fp16), 4-stage cp.async
#define BM 128
#define BN 256
#define BK 32
#define NT (HID / BK)             // 64
#define NSTAGE 4
#define STRIDE 20                 // h2 units per row: 16 data + 4 pad (conflict-free)
#define A_H2 (BM * STRIDE)        // 2560
#define B_H2 (BN * STRIDE)        // 5120
#define STAGE_H2 (A_H2 + B_H2)    // 7680
#define SMEM_BYTES (STAGE_H2 * NSTAGE * 4)   // 122880

// ---------------------------------------------------------------------------
// Static device scratch
// ---------------------------------------------------------------------------
__device__ __align__(16) __half g_h0[(size_t)M_PAD * HID];
__device__ __align__(16) __half g_h1[(size_t)M_PAD * HID];
__device__ __align__(16) __half g_wh[3][(size_t)HID * HID];  // fp16, transposed [n][k]
__device__ float g_amg[16448];
__device__ float g_mg0[262145];
__device__ float g_mg1[262145];

// ---------------------------------------------------------------------------
// PTX helpers
// ---------------------------------------------------------------------------
__device__ __forceinline__ void cp_async16(void* smem, const void* gmem) {
    uint32_t s = (uint32_t)__cvta_generic_to_shared(smem);
    asm volatile("cp.async.cg.shared.global [%0], [%1], 16;\n" :: "r"(s), "l"(gmem));
}
__device__ __forceinline__ void cp_commit() {
    asm volatile("cp.async.commit_group;\n" ::);
}
__device__ __forceinline__ void mma_f16(float* d, const uint32_t* a, const uint32_t* b) {
    asm volatile(
        "mma.sync.aligned.m16n8k16.row.col.f32.f16.f16.f32 "
        "{%0,%1,%2,%3}, {%4,%5,%6,%7}, {%8,%9}, {%0,%1,%2,%3};\n"
        : "+f"(d[0]), "+f"(d[1]), "+f"(d[2]), "+f"(d[3])
        : "r"(a[0]), "r"(a[1]), "r"(a[2]), "r"(a[3]), "r"(b[0]), "r"(b[1]));
}

// ---------------------------------------------------------------------------
// Weight transpose + fp16 convert:  out[n][k] = half(in[k][n])
// ---------------------------------------------------------------------------
__global__ void transpose_half(const float* __restrict__ in, __half* __restrict__ out) {
    __shared__ float t[32][33];
    int bx = blockIdx.x * 32, by = blockIdx.y * 32;   // bx: n-block, by: k-block
#pragma unroll
    for (int i = 0; i < 32; i += 8)
        t[threadIdx.y + i][threadIdx.x] = in[(size_t)(by + threadIdx.y + i) * HID + bx + threadIdx.x];
    __syncthreads();
#pragma unroll
    for (int i = 0; i < 32; i += 8)
        out[(size_t)(bx + threadIdx.y + i) * HID + by + threadIdx.x] =
            __float2half_rn(t[threadIdx.x][threadIdx.y + i]);
}

// ---------------------------------------------------------------------------
// Layer 0:  h0[i][j] = half(relu(xs[i]*w0[j] + b0[j])),  pad rows -> 0
// one thread per h2 pair
// ---------------------------------------------------------------------------
__global__ void layer0_kernel(const float* __restrict__ xs,
                              const float* __restrict__ w0,
                              const float* __restrict__ b0) {
    int idx = blockIdx.x * blockDim.x + threadIdx.x;
    if (idx >= M_PAD * (HID / 2)) return;
    int i = idx >> 10;
    int jh = idx & 1023;
    __half2 v = __float2half2_rn(0.0f);
    if (i < M_ROWS) {
        float x = xs[i];
        float2 w = *(const float2*)(w0 + 2 * jh);
        float2 b = *(const float2*)(b0 + 2 * jh);
        v = __floats2half2_rn(fmaxf(fmaf(x, w.x, b.x), 0.0f),
                              fmaxf(fmaf(x, w.y, b.y), 0.0f));
    }
    ((__half2*)g_h0)[idx] = v;
}

// ---------------------------------------------------------------------------
// Fused fp16 GEMM + bias + ReLU:  C = relu(A @ Wt^T + b)
// A: [M_PAD, 2048] half row-major.  Wt: [2048(n), 2048(k)] half row-major.
// sel==0: A=g_h0, C=g_h1 ; sel==1: A=g_h1, C=g_h0
// ---------------------------------------------------------------------------
__global__ void __launch_bounds__(256, 1)
gemm_f16_kernel(const __half* __restrict__ Wt,
                const float* __restrict__ bias,
                int sel) {
    const __half* __restrict__ A = sel ? g_h1 : g_h0;
    __half* __restrict__ C       = sel ? g_h0 : g_h1;

    extern __shared__ uint32_t sm[];   // h2 units

    const int t    = threadIdx.x;
    const int lane = t & 31;
    const int wid  = t >> 5;
    const int wm   = wid & 1;     // 0..1 -> 64-row slab
    const int wn   = wid >> 1;    // 0..3 -> 64-col slab
    const int g    = lane >> 2;   // 0..7
    const int tg   = lane & 3;    // 0..3

    const int bm = blockIdx.y * BM;
    const int bn = blockIdx.x * BN;

    float acc[4][8][4];
#pragma unroll
    for (int i = 0; i < 4; i++)
#pragma unroll
        for (int j = 0; j < 8; j++)
#pragma unroll
            for (int r = 0; r < 4; r++) acc[i][j][r] = 0.0f;

    // global->smem: 16B chunks of 8 halfs. A: 512 chunks, B: 1024 chunks.
    auto load_tile = [&](int kt, int stage) {
        uint32_t* As = sm + stage * STAGE_H2;
        uint32_t* Bs = As + A_H2;
        const int kh0 = kt * (BK / 2);          // h2 offset in global k
#pragma unroll
        for (int it = 0; it < 2; it++) {
            int chunk = t + it * 256;           // 0..511
            int row = chunk >> 2, c = chunk & 3;
            cp_async16(&As[row * STRIDE + c * 4],
                       (const __half2*)A + (size_t)(bm + row) * (HID / 2) + kh0 + c * 4);
        }
#pragma unroll
        for (int it = 0; it < 4; it++) {
            int chunk = t + it * 256;           // 0..1023
            int row = chunk >> 2, c = chunk & 3;
            cp_async16(&Bs[row * STRIDE + c * 4],
                       (const __half2*)Wt + (size_t)(bn + row) * (HID / 2) + kh0 + c * 4);
        }
        cp_commit();
    };

    load_tile(0, 0);
    load_tile(1, 1);
    load_tile(2, 2);

#pragma unroll 1
    for (int kt = 0; kt < NT; kt++) {
        asm volatile("cp.async.wait_group 2;\n" ::);
        __syncthreads();

        const uint32_t* As = sm + (kt & (NSTAGE - 1)) * STAGE_H2;
        const uint32_t* Bs = As + A_H2;
        const uint32_t* aptr = As + (wm * 64 + g) * STRIDE + tg;
        const uint32_t* bptr = Bs + (wn * 64 + g) * STRIDE + tg;

#pragma unroll
        for (int kk = 0; kk < 2; kk++) {
            const int kb = kk * 8;              // h2 offset within stage row
            uint32_t af[4][4];
            uint32_t bf[8][2];
#pragma unroll
            for (int tm = 0; tm < 4; tm++) {
                af[tm][0] = aptr[(tm * 16) * STRIDE + kb];
                af[tm][1] = aptr[(tm * 16 + 8) * STRIDE + kb];
                af[tm][2] = aptr[(tm * 16) * STRIDE + kb + 4];
                af[tm][3] = aptr[(tm * 16 + 8) * STRIDE + kb + 4];
            }
#pragma unroll
            for (int tn = 0; tn < 8; tn++) {
                bf[tn][0] = bptr[(tn * 8) * STRIDE + kb];
                bf[tn][1] = bptr[(tn * 8) * STRIDE + kb + 4];
            }
#pragma unroll
            for (int tm = 0; tm < 4; tm++)
#pragma unroll
                for (int tn = 0; tn < 8; tn++)
                    mma_f16(acc[tm][tn], af[tm], bf[tn]);
        }

        // prefetch kt+3 into the stage freed at iteration kt-1
        if (kt + 3 < NT) load_tile(kt + 3, (kt + 3) & (NSTAGE - 1));
        else             cp_commit();           // keep group count uniform
    }

    // Epilogue: bias + relu -> half2 store
#pragma unroll
    for (int tn = 0; tn < 8; tn++) {
        int c0 = bn + wn * 64 + tn * 8 + 2 * tg;
        float bv0 = __ldg(&bias[c0]);
        float bv1 = __ldg(&bias[c0 + 1]);
#pragma unroll
        for (int tm = 0; tm < 4; tm++) {
            int r0 = bm + wm * 64 + tm * 16 + g;
            __half2 v0 = __floats2half2_rn(fmaxf(acc[tm][tn][0] + bv0, 0.0f),
                                           fmaxf(acc[tm][tn][1] + bv1, 0.0f));
            __half2 v1 = __floats2half2_rn(fmaxf(acc[tm][tn][2] + bv0, 0.0f),
                                           fmaxf(acc[tm][tn][3] + bv1, 0.0f));
            *(__half2*)(C + (size_t)r0 * HID + c0) = v0;
            *(__half2*)(C + (size_t)(r0 + 8) * HID + c0) = v1;
        }
    }
}

// ---------------------------------------------------------------------------
// Final layer GEMV: Amg[i] = relu(dot(h1[i,:], w4) + b4)   (h1 is fp16)
// ---------------------------------------------------------------------------
__global__ void gemv_kernel(const float* __restrict__ w4,
                            const float* __restrict__ b4) {
    int warp = (blockIdx.x * blockDim.x + threadIdx.x) >> 5;
    int lane = threadIdx.x & 31;
    if (warp >= M_ROWS) return;
    const __half2* hv = (const __half2*)(g_h1 + (size_t)warp * HID);
    const float2* wv = (const float2*)w4;
    float s = 0.0f;
#pragma unroll
    for (int i = lane; i < HID / 2; i += 32) {
        float2 a = __half22float2(hv[i]);
        float2 b = wv[i];
        s = fmaf(a.x, b.x, fmaf(a.y, b.y, s));
    }
#pragma unroll
    for (int off = 16; off > 0; off >>= 1)
        s += __shfl_xor_sync(0xFFFFFFFFu, s, off);
    if (lane == 0) g_amg[warp] = fmaxf(s + b4[0], 0.0f);
}

// ---------------------------------------------------------------------------
// Multigrid level: interp (2n-1) + inline scatter of the 8 band values.
// ---------------------------------------------------------------------------
__global__ void mg_kernel(int lvl, const int* __restrict__ nbrs, float* dout) {
    const float* in;
    float* out;
    switch (lvl) {
        case 0: in = g_amg + 40; out = g_mg0; break;
        case 1: in = g_mg0;      out = g_mg1; break;
        case 2: in = g_mg1;      out = g_mg0; break;
        case 3: in = g_mg0;      out = g_mg1; break;
        default: in = g_mg1;     out = dout;  break;
    }
    const int n_out = 2 * ((16384 << lvl) + 1) - 1;
    const int* nbr8 = nbrs + lvl * 8;
    const float* band = g_amg + 8 * (4 - lvl);

    int p = blockIdx.x * blockDim.x + threadIdx.x;
    if (p >= n_out) return;
    float v;
    if (p & 1) {
        int h = p >> 1;
        v = 0.5f * (in[h] + in[h + 1]);
#pragma unroll
        for (int j = 0; j < 8; j++)
            if (p == nbr8[j]) v = band[j];
    } else {
        v = in[p >> 1];
    }
    out[p] = v;
}

// ---------------------------------------------------------------------------
// Launch
// ---------------------------------------------------------------------------
extern "C" void kernel_launch(void* const* d_in, const int* in_sizes, int n_in,
                              void* d_out, int out_size) {
    const float *xs, *w0, *b0, *w1, *b1, *w2, *b2, *w3, *b3, *w4, *b4;
    const int* nbrs;

    if (n_in >= 2 && in_sizes[1] == 40) {
        xs   = (const float*)d_in[0];
        nbrs = (const int*)d_in[1];
        w0 = (const float*)d_in[4];  b0 = (const float*)d_in[5];
        w1 = (const float*)d_in[6];  b1 = (const float*)d_in[7];
        w2 = (const float*)d_in[8];  b2 = (const float*)d_in[9];
        w3 = (const float*)d_in[10]; b3 = (const float*)d_in[11];
        w4 = (const float*)d_in[12]; b4 = (const float*)d_in[13];
    } else {
        xs   = (const float*)d_in[0];
        w0 = (const float*)d_in[1];  b0 = (const float*)d_in[2];
        w1 = (const float*)d_in[3];  b1 = (const float*)d_in[4];
        w2 = (const float*)d_in[5];  b2 = (const float*)d_in[6];
        w3 = (const float*)d_in[7];  b3 = (const float*)d_in[8];
        w4 = (const float*)d_in[9];  b4 = (const float*)d_in[10];
        nbrs = (const int*)d_in[11];
    }

    void* p_wh;
    cudaGetSymbolAddress(&p_wh, g_wh);
    __half* wh0 = (__half*)p_wh;
    __half* wh1 = wh0 + (size_t)HID * HID;
    __half* wh2 = wh1 + (size_t)HID * HID;

    cudaFuncSetAttribute(gemm_f16_kernel,
                         cudaFuncAttributeMaxDynamicSharedMemorySize, SMEM_BYTES);

    // Weight transpose + fp16 convert
    {
        dim3 gr(HID / 32, HID / 32), bl(32, 8);
        transpose_half<<<gr, bl>>>(w1, wh0);
        transpose_half<<<gr, bl>>>(w2, wh1);
        transpose_half<<<gr, bl>>>(w3, wh2);
    }

    // Layer 0 -> g_h0 (fp16)
    layer0_kernel<<<(M_PAD * (HID / 2) + 255) / 256, 256>>>(xs, w0, b0);

    // Three hidden GEMMs (fp16 tensor cores, fused bias+relu)
    dim3 grid(HID / BN, M_PAD / BM);  // (8, 129)
    gemm_f16_kernel<<<grid, 256, SMEM_BYTES>>>(wh0, b1, 0); // h0 -> h1
    gemm_f16_kernel<<<grid, 256, SMEM_BYTES>>>(wh1, b2, 1); // h1 -> h0
    gemm_f16_kernel<<<grid, 256, SMEM_BYTES>>>(wh2, b3, 0); // h0 -> h1

    // Final GEMV -> g_amg
    gemv_kernel<<<(M_ROWS * 32 + 255) / 256, 256>>>(w4, b4);

    // Multigrid reconstruction
    for (int lvl = 0; lvl < K_LEV; lvl++) {
        int n_out_l = (16384 << (lvl + 1)) + 1;
        mg_kernel<<<(n_out_l + 255) / 256, 256>>>(lvl, nbrs, (float*)d_out);
    }
    (void)out_size;
}

// round 5
// speedup vs baseline: 2.4182x; 1.2361x over previous
#include <cuda_runtime.h>
#include <cuda_fp16.h>
#include <cstdint>

// Problem constants
#define M_ROWS   16425
#define M_PAD    16512            // 129 * 128
#define HID      2048
#define K_LEV    5

// GEMM tiling: CTA 128x256, 8 warps of 64x64, BK=64 (fp16), 3-stage cp.async
#define BM 128
#define BN 256
#define BK 64
#define NT (HID / BK)             // 32
#define NSTAGE 3
#define STRIDE 36                 // h2 per row: 32 data + 4 pad (9x16B, gcd(9,8)=1)
#define A_H2 (BM * STRIDE)        // 4608
#define B_H2 (BN * STRIDE)        // 9216
#define STAGE_H2 (A_H2 + B_H2)    // 13824
#define SMEM_BYTES (STAGE_H2 * NSTAGE * 4)   // 165888

// ---------------------------------------------------------------------------
// Static device scratch
// ---------------------------------------------------------------------------
__device__ __align__(16) __half g_h0[(size_t)M_PAD * HID];
__device__ __align__(16) __half g_h1[(size_t)M_PAD * HID];
__device__ __align__(16) __half g_wh[3][(size_t)HID * HID];  // fp16, transposed [n][k]
__device__ float g_amg[16448];
__device__ float g_mg0[262145];
__device__ float g_mg1[262145];

// ---------------------------------------------------------------------------
// PTX helpers
// ---------------------------------------------------------------------------
__device__ __forceinline__ void cp_async16(void* smem, const void* gmem) {
    uint32_t s = (uint32_t)__cvta_generic_to_shared(smem);
    asm volatile("cp.async.cg.shared.global [%0], [%1], 16;\n" :: "r"(s), "l"(gmem));
}
__device__ __forceinline__ void cp_commit() {
    asm volatile("cp.async.commit_group;\n" ::);
}
__device__ __forceinline__ void ldsm_x4(uint32_t& r0, uint32_t& r1, uint32_t& r2,
                                        uint32_t& r3, uint32_t saddr) {
    asm volatile("ldmatrix.sync.aligned.m8n8.x4.shared.b16 {%0,%1,%2,%3}, [%4];"
                 : "=r"(r0), "=r"(r1), "=r"(r2), "=r"(r3) : "r"(saddr));
}
__device__ __forceinline__ void mma_f16(float* d, const uint32_t* a, const uint32_t* b) {
    asm volatile(
        "mma.sync.aligned.m16n8k16.row.col.f32.f16.f16.f32 "
        "{%0,%1,%2,%3}, {%4,%5,%6,%7}, {%8,%9}, {%0,%1,%2,%3};\n"
        : "+f"(d[0]), "+f"(d[1]), "+f"(d[2]), "+f"(d[3])
        : "r"(a[0]), "r"(a[1]), "r"(a[2]), "r"(a[3]), "r"(b[0]), "r"(b[1]));
}

// ---------------------------------------------------------------------------
// Weight transpose + fp16 convert:  out[n][k] = half(in[k][n])
// ---------------------------------------------------------------------------
__global__ void transpose_half(const float* __restrict__ in, __half* __restrict__ out) {
    __shared__ float t[32][33];
    int bx = blockIdx.x * 32, by = blockIdx.y * 32;   // bx: n-block, by: k-block
#pragma unroll
    for (int i = 0; i < 32; i += 8)
        t[threadIdx.y + i][threadIdx.x] = in[(size_t)(by + threadIdx.y + i) * HID + bx + threadIdx.x];
    __syncthreads();
#pragma unroll
    for (int i = 0; i < 32; i += 8)
        out[(size_t)(bx + threadIdx.y + i) * HID + by + threadIdx.x] =
            __float2half_rn(t[threadIdx.x][threadIdx.y + i]);
}

// ---------------------------------------------------------------------------
// Layer 0 (vectorized): each thread writes 8 halfs (16B)
// ---------------------------------------------------------------------------
__global__ void layer0_kernel(const float* __restrict__ xs,
                              const float* __restrict__ w0,
                              const float* __restrict__ b0) {
    int idx = blockIdx.x * blockDim.x + threadIdx.x;     // chunk of 8 outputs
    if (idx >= M_PAD * (HID / 8)) return;
    int i = idx >> 8;            // row
    int jc = (idx & 255) * 8;    // col base
    __half2 v[4];
    if (i < M_ROWS) {
        float x = xs[i];
#pragma unroll
        for (int q = 0; q < 4; q++) {
            float2 w = *(const float2*)(w0 + jc + 2 * q);
            float2 b = *(const float2*)(b0 + jc + 2 * q);
            v[q] = __floats2half2_rn(fmaxf(fmaf(x, w.x, b.x), 0.0f),
                                     fmaxf(fmaf(x, w.y, b.y), 0.0f));
        }
    } else {
#pragma unroll
        for (int q = 0; q < 4; q++) v[q] = __float2half2_rn(0.0f);
    }
    *(uint4*)(g_h0 + (size_t)i * HID + jc) = *(uint4*)v;
}

// ---------------------------------------------------------------------------
// Fused fp16 GEMM + bias + ReLU:  C = relu(A @ Wt^T + b)
// A: [M_PAD, 2048] half row-major.  Wt: [2048(n), 2048(k)] half row-major.
// ---------------------------------------------------------------------------
__global__ void __launch_bounds__(256, 1)
gemm_f16_kernel(const __half* __restrict__ Wt,
                const float* __restrict__ bias,
                int sel) {
    const __half* __restrict__ A = sel ? g_h1 : g_h0;
    __half* __restrict__ C       = sel ? g_h0 : g_h1;

    extern __shared__ uint32_t sm[];   // h2 units

    const int t    = threadIdx.x;
    const int lane = t & 31;
    const int wid  = t >> 5;
    const int wm   = wid & 1;     // 0..1 -> 64-row slab
    const int wn   = wid >> 1;    // 0..3 -> 64-col slab
    const int g    = lane >> 2;   // 0..7
    const int tg   = lane & 3;    // 0..3

    const int bm = blockIdx.y * BM;
    const int bn = blockIdx.x * BN;

    float acc[4][8][4];
#pragma unroll
    for (int i = 0; i < 4; i++)
#pragma unroll
        for (int j = 0; j < 8; j++)
#pragma unroll
            for (int r = 0; r < 4; r++) acc[i][j][r] = 0.0f;

    // ldmatrix lane-address components (h2 index within stage)
    const int a_idx = (wm * 64 + (lane & 15)) * STRIDE + ((lane >> 4) << 2);
    const int b_idx = (wn * 64 + ((lane >> 4) << 3) + (lane & 7)) * STRIDE
                      + (((lane >> 3) & 1) << 2);

    // global->smem: A 1024 chunks of 16B, B 2048 chunks; 256 threads
    auto load_tile = [&](int kt, int stage) {
        uint32_t* As = sm + stage * STAGE_H2;
        uint32_t* Bs = As + A_H2;
        const int kh0 = kt * (BK / 2);          // h2 offset in global k
#pragma unroll
        for (int it = 0; it < 4; it++) {
            int chunk = t + it * 256;           // 0..1023
            int row = chunk >> 3, c = chunk & 7;
            cp_async16(&As[row * STRIDE + c * 4],
                       (const __half2*)A + (size_t)(bm + row) * (HID / 2) + kh0 + c * 4);
        }
#pragma unroll
        for (int it = 0; it < 8; it++) {
            int chunk = t + it * 256;           // 0..2047
            int row = chunk >> 3, c = chunk & 7;
            cp_async16(&Bs[row * STRIDE + c * 4],
                       (const __half2*)Wt + (size_t)(bn + row) * (HID / 2) + kh0 + c * 4);
        }
        cp_commit();
    };

    load_tile(0, 0);
    load_tile(1, 1);

#pragma unroll 1
    for (int kt = 0; kt < NT; kt++) {
        asm volatile("cp.async.wait_group 1;\n" ::);
        __syncthreads();

        const int sbase = (kt % NSTAGE) * STAGE_H2;
        const uint32_t a_addr0 = (uint32_t)__cvta_generic_to_shared(sm + sbase + a_idx);
        const uint32_t b_addr0 = (uint32_t)__cvta_generic_to_shared(sm + sbase + A_H2 + b_idx);

#pragma unroll
        for (int kk = 0; kk < 4; kk++) {
            const uint32_t koff = kk * 8 * 4;   // kb h2 -> bytes
            uint32_t af[4][4];
            uint32_t bf[4][4];                  // pair p -> tn 2p, 2p+1
#pragma unroll
            for (int tm = 0; tm < 4; tm++)
                ldsm_x4(af[tm][0], af[tm][1], af[tm][2], af[tm][3],
                        a_addr0 + koff + tm * (16 * STRIDE * 4));
#pragma unroll
            for (int p = 0; p < 4; p++)
                ldsm_x4(bf[p][0], bf[p][1], bf[p][2], bf[p][3],
                        b_addr0 + koff + p * (16 * STRIDE * 4));
#pragma unroll
            for (int tm = 0; tm < 4; tm++)
#pragma unroll
                for (int tn = 0; tn < 8; tn++)
                    mma_f16(acc[tm][tn], af[tm], &bf[tn >> 1][(tn & 1) * 2]);
        }

        // prefetch kt+2 into the stage consumed at kt-1 (sync above retired it)
        if (kt + 2 < NT) load_tile(kt + 2, (kt + 2) % NSTAGE);
        else             cp_commit();           // uniform group accounting
    }

    // Epilogue: bias + relu -> half2 store
#pragma unroll
    for (int tn = 0; tn < 8; tn++) {
        int c0 = bn + wn * 64 + tn * 8 + 2 * tg;
        float bv0 = __ldg(&bias[c0]);
        float bv1 = __ldg(&bias[c0 + 1]);
#pragma unroll
        for (int tm = 0; tm < 4; tm++) {
            int r0 = bm + wm * 64 + tm * 16 + g;
            __half2 v0 = __floats2half2_rn(fmaxf(acc[tm][tn][0] + bv0, 0.0f),
                                           fmaxf(acc[tm][tn][1] + bv1, 0.0f));
            __half2 v1 = __floats2half2_rn(fmaxf(acc[tm][tn][2] + bv0, 0.0f),
                                           fmaxf(acc[tm][tn][3] + bv1, 0.0f));
            *(__half2*)(C + (size_t)r0 * HID + c0) = v0;
            *(__half2*)(C + (size_t)(r0 + 8) * HID + c0) = v1;
        }
    }
}

// ---------------------------------------------------------------------------
// Final layer GEMV: Amg[i] = relu(dot(h1[i,:], w4) + b4)   (h1 is fp16)
// ---------------------------------------------------------------------------
__global__ void gemv_kernel(const float* __restrict__ w4,
                            const float* __restrict__ b4) {
    int warp = (blockIdx.x * blockDim.x + threadIdx.x) >> 5;
    int lane = threadIdx.x & 31;
    if (warp >= M_ROWS) return;
    const __half2* hv = (const __half2*)(g_h1 + (size_t)warp * HID);
    const float2* wv = (const float2*)w4;
    float s = 0.0f;
#pragma unroll
    for (int i = lane; i < HID / 2; i += 32) {
        float2 a = __half22float2(hv[i]);
        float2 b = wv[i];
        s = fmaf(a.x, b.x, fmaf(a.y, b.y, s));
    }
#pragma unroll
    for (int off = 16; off > 0; off >>= 1)
        s += __shfl_xor_sync(0xFFFFFFFFu, s, off);
    if (lane == 0) g_amg[warp] = fmaxf(s + b4[0], 0.0f);
}

// ---------------------------------------------------------------------------
// Multigrid level: interp (2n-1) + inline scatter of the 8 band values.
// ---------------------------------------------------------------------------
__global__ void mg_kernel(int lvl, const int* __restrict__ nbrs, float* dout) {
    const float* in;
    float* out;
    switch (lvl) {
        case 0: in = g_amg + 40; out = g_mg0; break;
        case 1: in = g_mg0;      out = g_mg1; break;
        case 2: in = g_mg1;      out = g_mg0; break;
        case 3: in = g_mg0;      out = g_mg1; break;
        default: in = g_mg1;     out = dout;  break;
    }
    const int n_out = 2 * ((16384 << lvl) + 1) - 1;
    const int* nbr8 = nbrs + lvl * 8;
    const float* band = g_amg + 8 * (4 - lvl);

    int p = blockIdx.x * blockDim.x + threadIdx.x;
    if (p >= n_out) return;
    float v;
    if (p & 1) {
        int h = p >> 1;
        v = 0.5f * (in[h] + in[h + 1]);
#pragma unroll
        for (int j = 0; j < 8; j++)
            if (p == nbr8[j]) v = band[j];
    } else {
        v = in[p >> 1];
    }
    out[p] = v;
}

// ---------------------------------------------------------------------------
// Launch
// ---------------------------------------------------------------------------
extern "C" void kernel_launch(void* const* d_in, const int* in_sizes, int n_in,
                              void* d_out, int out_size) {
    const float *xs, *w0, *b0, *w1, *b1, *w2, *b2, *w3, *b3, *w4, *b4;
    const int* nbrs;

    if (n_in >= 2 && in_sizes[1] == 40) {
        xs   = (const float*)d_in[0];
        nbrs = (const int*)d_in[1];
        w0 = (const float*)d_in[4];  b0 = (const float*)d_in[5];
        w1 = (const float*)d_in[6];  b1 = (const float*)d_in[7];
        w2 = (const float*)d_in[8];  b2 = (const float*)d_in[9];
        w3 = (const float*)d_in[10]; b3 = (const float*)d_in[11];
        w4 = (const float*)d_in[12]; b4 = (const float*)d_in[13];
    } else {
        xs   = (const float*)d_in[0];
        w0 = (const float*)d_in[1];  b0 = (const float*)d_in[2];
        w1 = (const float*)d_in[3];  b1 = (const float*)d_in[4];
        w2 = (const float*)d_in[5];  b2 = (const float*)d_in[6];
        w3 = (const float*)d_in[7];  b3 = (const float*)d_in[8];
        w4 = (const float*)d_in[9];  b4 = (const float*)d_in[10];
        nbrs = (const int*)d_in[11];
    }

    void* p_wh;
    cudaGetSymbolAddress(&p_wh, g_wh);
    __half* wh0 = (__half*)p_wh;
    __half* wh1 = wh0 + (size_t)HID * HID;
    __half* wh2 = wh1 + (size_t)HID * HID;

    cudaFuncSetAttribute(gemm_f16_kernel,
                         cudaFuncAttributeMaxDynamicSharedMemorySize, SMEM_BYTES);

    // Weight transpose + fp16 convert
    {
        dim3 gr(HID / 32, HID / 32), bl(32, 8);
        transpose_half<<<gr, bl>>>(w1, wh0);
        transpose_half<<<gr, bl>>>(w2, wh1);
        transpose_half<<<gr, bl>>>(w3, wh2);
    }

    // Layer 0 -> g_h0 (fp16)
    layer0_kernel<<<(M_PAD * (HID / 8) + 255) / 256, 256>>>(xs, w0, b0);

    // Three hidden GEMMs (fp16 tensor cores, fused bias+relu)
    dim3 grid(HID / BN, M_PAD / BM);  // (8, 129)
    gemm_f16_kernel<<<grid, 256, SMEM_BYTES>>>(wh0, b1, 0); // h0 -> h1
    gemm_f16_kernel<<<grid, 256, SMEM_BYTES>>>(wh1, b2, 1); // h1 -> h0
    gemm_f16_kernel<<<grid, 256, SMEM_BYTES>>>(wh2, b3, 0); // h0 -> h1

    // Final GEMV -> g_amg
    gemv_kernel<<<(M_ROWS * 32 + 255) / 256, 256>>>(w4, b4);

    // Multigrid reconstruction
    for (int lvl = 0; lvl < K_LEV; lvl++) {
        int n_out_l = (16384 << (lvl + 1)) + 1;
        mg_kernel<<<(n_out_l + 255) / 256, 256>>>(lvl, nbrs, (float*)d_out);
    }
    (void)out_size;
}

// round 6
// speedup vs baseline: 2.4735x; 1.0229x over previous
#include <cuda_runtime.h>
#include <cuda_fp16.h>
#include <cstdint>

// Problem constants
#define M_ROWS   16425
#define M_PAD    16512            // 129 * 128
#define HID      2048
#define K_LEV    5

// GEMM tiling: CTA 128x256, 8 warps of 64x64, BK=64 (fp16), 3-stage cp.async
#define BM 128
#define BN 256
#define BK 64
#define NT (HID / BK)             // 32
#define NSTAGE 3
#define STRIDE 36                 // h2 per row: 32 data + 4 pad (9x16B, gcd(9,8)=1)
#define A_H2 (BM * STRIDE)        // 4608
#define B_H2 (BN * STRIDE)        // 9216
#define STAGE_H2 (A_H2 + B_H2)    // 13824
#define SMEM_BYTES (STAGE_H2 * NSTAGE * 4)   // 165888

// ---------------------------------------------------------------------------
// Static device scratch
// ---------------------------------------------------------------------------
__device__ __align__(16) __half g_h0[(size_t)M_PAD * HID];
__device__ __align__(16) __half g_h1[(size_t)M_PAD * HID];
__device__ __align__(16) __half g_wh[3][(size_t)HID * HID];  // fp16, transposed [n][k]
__device__ float g_amg[16448];
__device__ float g_mg0[262145];
__device__ float g_mg1[262145];

// ---------------------------------------------------------------------------
// PTX helpers
// ---------------------------------------------------------------------------
__device__ __forceinline__ void cp_async16(void* smem, const void* gmem) {
    uint32_t s = (uint32_t)__cvta_generic_to_shared(smem);
    asm volatile("cp.async.cg.shared.global [%0], [%1], 16;\n" :: "r"(s), "l"(gmem));
}
__device__ __forceinline__ void cp_commit() {
    asm volatile("cp.async.commit_group;\n" ::);
}
__device__ __forceinline__ void ldsm_x4(uint32_t& r0, uint32_t& r1, uint32_t& r2,
                                        uint32_t& r3, uint32_t saddr) {
    asm volatile("ldmatrix.sync.aligned.m8n8.x4.shared.b16 {%0,%1,%2,%3}, [%4];"
                 : "=r"(r0), "=r"(r1), "=r"(r2), "=r"(r3) : "r"(saddr));
}
__device__ __forceinline__ void mma_f16(float* d, const uint32_t* a, const uint32_t* b) {
    asm volatile(
        "mma.sync.aligned.m16n8k16.row.col.f32.f16.f16.f32 "
        "{%0,%1,%2,%3}, {%4,%5,%6,%7}, {%8,%9}, {%0,%1,%2,%3};\n"
        : "+f"(d[0]), "+f"(d[1]), "+f"(d[2]), "+f"(d[3])
        : "r"(a[0]), "r"(a[1]), "r"(a[2]), "r"(a[3]), "r"(b[0]), "r"(b[1]));
}

// ---------------------------------------------------------------------------
// Fused weight transpose + fp16 convert for all 3 layers (z selects layer)
// out[n][k] = half(in[k][n])
// ---------------------------------------------------------------------------
__global__ void transpose_half3(const float* __restrict__ in0,
                                const float* __restrict__ in1,
                                const float* __restrict__ in2,
                                __half* __restrict__ outbase) {
    const float* in = (blockIdx.z == 0) ? in0 : (blockIdx.z == 1) ? in1 : in2;
    __half* out = outbase + (size_t)blockIdx.z * HID * HID;
    __shared__ float t[32][33];
    int bx = blockIdx.x * 32, by = blockIdx.y * 32;   // bx: n-block, by: k-block
#pragma unroll
    for (int i = 0; i < 32; i += 8)
        t[threadIdx.y + i][threadIdx.x] = in[(size_t)(by + threadIdx.y + i) * HID + bx + threadIdx.x];
    __syncthreads();
#pragma unroll
    for (int i = 0; i < 32; i += 8)
        out[(size_t)(bx + threadIdx.y + i) * HID + by + threadIdx.x] =
            __float2half_rn(t[threadIdx.x][threadIdx.y + i]);
}

// ---------------------------------------------------------------------------
// Layer 0 (register-cached weights): thread owns 8 cols, loops 32 rows.
// h0[i][j] = half(relu(xs[i]*w0[j] + b0[j])),  pad rows -> 0
// ---------------------------------------------------------------------------
#define L0_ROWS 32
__global__ void __launch_bounds__(256)
layer0_kernel(const float* __restrict__ xs,
              const float* __restrict__ w0,
              const float* __restrict__ b0) {
    const int jc = threadIdx.x * 8;              // 256 threads cover 2048 cols
    float w[8], b[8];
#pragma unroll
    for (int q = 0; q < 2; q++) {
        *(float4*)(w + 4 * q) = *(const float4*)(w0 + jc + 4 * q);
        *(float4*)(b + 4 * q) = *(const float4*)(b0 + jc + 4 * q);
    }
    const int r0 = blockIdx.x * L0_ROWS;
#pragma unroll 1
    for (int r = r0; r < r0 + L0_ROWS; r++) {
        __half2 v[4];
        if (r < M_ROWS) {
            const float x = __ldg(&xs[r]);
#pragma unroll
            for (int q = 0; q < 4; q++)
                v[q] = __floats2half2_rn(fmaxf(fmaf(x, w[2 * q], b[2 * q]), 0.0f),
                                         fmaxf(fmaf(x, w[2 * q + 1], b[2 * q + 1]), 0.0f));
        } else {
#pragma unroll
            for (int q = 0; q < 4; q++) v[q] = __float2half2_rn(0.0f);
        }
        *(uint4*)(g_h0 + (size_t)r * HID + jc) = *(uint4*)v;
    }
}

// ---------------------------------------------------------------------------
// Fused fp16 GEMM + bias + ReLU:  C = relu(A @ Wt^T + b)   [UNCHANGED]
// ---------------------------------------------------------------------------
__global__ void __launch_bounds__(256, 1)
gemm_f16_kernel(const __half* __restrict__ Wt,
                const float* __restrict__ bias,
                int sel) {
    const __half* __restrict__ A = sel ? g_h1 : g_h0;
    __half* __restrict__ C       = sel ? g_h0 : g_h1;

    extern __shared__ uint32_t sm[];   // h2 units

    const int t    = threadIdx.x;
    const int lane = t & 31;
    const int wid  = t >> 5;
    const int wm   = wid & 1;     // 0..1 -> 64-row slab
    const int wn   = wid >> 1;    // 0..3 -> 64-col slab
    const int g    = lane >> 2;   // 0..7
    const int tg   = lane & 3;    // 0..3

    const int bm = blockIdx.y * BM;
    const int bn = blockIdx.x * BN;

    float acc[4][8][4];
#pragma unroll
    for (int i = 0; i < 4; i++)
#pragma unroll
        for (int j = 0; j < 8; j++)
#pragma unroll
            for (int r = 0; r < 4; r++) acc[i][j][r] = 0.0f;

    const int a_idx = (wm * 64 + (lane & 15)) * STRIDE + ((lane >> 4) << 2);
    const int b_idx = (wn * 64 + ((lane >> 4) << 3) + (lane & 7)) * STRIDE
                      + (((lane >> 3) & 1) << 2);

    auto load_tile = [&](int kt, int stage) {
        uint32_t* As = sm + stage * STAGE_H2;
        uint32_t* Bs = As + A_H2;
        const int kh0 = kt * (BK / 2);
#pragma unroll
        for (int it = 0; it < 4; it++) {
            int chunk = t + it * 256;
            int row = chunk >> 3, c = chunk & 7;
            cp_async16(&As[row * STRIDE + c * 4],
                       (const __half2*)A + (size_t)(bm + row) * (HID / 2) + kh0 + c * 4);
        }
#pragma unroll
        for (int it = 0; it < 8; it++) {
            int chunk = t + it * 256;
            int row = chunk >> 3, c = chunk & 7;
            cp_async16(&Bs[row * STRIDE + c * 4],
                       (const __half2*)Wt + (size_t)(bn + row) * (HID / 2) + kh0 + c * 4);
        }
        cp_commit();
    };

    load_tile(0, 0);
    load_tile(1, 1);

#pragma unroll 1
    for (int kt = 0; kt < NT; kt++) {
        asm volatile("cp.async.wait_group 1;\n" ::);
        __syncthreads();

        const int sbase = (kt % NSTAGE) * STAGE_H2;
        const uint32_t a_addr0 = (uint32_t)__cvta_generic_to_shared(sm + sbase + a_idx);
        const uint32_t b_addr0 = (uint32_t)__cvta_generic_to_shared(sm + sbase + A_H2 + b_idx);

#pragma unroll
        for (int kk = 0; kk < 4; kk++) {
            const uint32_t koff = kk * 8 * 4;
            uint32_t af[4][4];
            uint32_t bf[4][4];
#pragma unroll
            for (int tm = 0; tm < 4; tm++)
                ldsm_x4(af[tm][0], af[tm][1], af[tm][2], af[tm][3],
                        a_addr0 + koff + tm * (16 * STRIDE * 4));
#pragma unroll
            for (int p = 0; p < 4; p++)
                ldsm_x4(bf[p][0], bf[p][1], bf[p][2], bf[p][3],
                        b_addr0 + koff + p * (16 * STRIDE * 4));
#pragma unroll
            for (int tm = 0; tm < 4; tm++)
#pragma unroll
                for (int tn = 0; tn < 8; tn++)
                    mma_f16(acc[tm][tn], af[tm], &bf[tn >> 1][(tn & 1) * 2]);
        }

        if (kt + 2 < NT) load_tile(kt + 2, (kt + 2) % NSTAGE);
        else             cp_commit();
    }

    // Epilogue: bias + relu -> half2 store
#pragma unroll
    for (int tn = 0; tn < 8; tn++) {
        int c0 = bn + wn * 64 + tn * 8 + 2 * tg;
        float bv0 = __ldg(&bias[c0]);
        float bv1 = __ldg(&bias[c0 + 1]);
#pragma unroll
        for (int tm = 0; tm < 4; tm++) {
            int r0 = bm + wm * 64 + tm * 16 + g;
            __half2 v0 = __floats2half2_rn(fmaxf(acc[tm][tn][0] + bv0, 0.0f),
                                           fmaxf(acc[tm][tn][1] + bv1, 0.0f));
            __half2 v1 = __floats2half2_rn(fmaxf(acc[tm][tn][2] + bv0, 0.0f),
                                           fmaxf(acc[tm][tn][3] + bv1, 0.0f));
            *(__half2*)(C + (size_t)r0 * HID + c0) = v0;
            *(__half2*)(C + (size_t)(r0 + 8) * HID + c0) = v1;
        }
    }
}

// ---------------------------------------------------------------------------
// Final layer GEMV (vectorized): Amg[i] = relu(dot(h1[i,:], w4) + b4)
// ---------------------------------------------------------------------------
__global__ void gemv_kernel(const float* __restrict__ w4,
                            const float* __restrict__ b4) {
    int warp = (blockIdx.x * blockDim.x + threadIdx.x) >> 5;
    int lane = threadIdx.x & 31;
    if (warp >= M_ROWS) return;
    const uint4* hv = (const uint4*)(g_h1 + (size_t)warp * HID);   // 8 halfs
    const float4* wv = (const float4*)w4;
    float s = 0.0f;
#pragma unroll
    for (int i = lane; i < HID / 8; i += 32) {
        uint4 pk = hv[i];
        const __half2* h = (const __half2*)&pk;
        float4 wa = wv[2 * i];
        float4 wb = wv[2 * i + 1];
        float2 a0 = __half22float2(h[0]);
        float2 a1 = __half22float2(h[1]);
        float2 a2 = __half22float2(h[2]);
        float2 a3 = __half22float2(h[3]);
        s = fmaf(a0.x, wa.x, s); s = fmaf(a0.y, wa.y, s);
        s = fmaf(a1.x, wa.z, s); s = fmaf(a1.y, wa.w, s);
        s = fmaf(a2.x, wb.x, s); s = fmaf(a2.y, wb.y, s);
        s = fmaf(a3.x, wb.z, s); s = fmaf(a3.y, wb.w, s);
    }
#pragma unroll
    for (int off = 16; off > 0; off >>= 1)
        s += __shfl_xor_sync(0xFFFFFFFFu, s, off);
    if (lane == 0) g_amg[warp] = fmaxf(s + b4[0], 0.0f);
}

// ---------------------------------------------------------------------------
// Multigrid level: interp (2n-1) + inline scatter of the 8 band values.
// ---------------------------------------------------------------------------
__global__ void mg_kernel(int lvl, const int* __restrict__ nbrs, float* dout) {
    const float* in;
    float* out;
    switch (lvl) {
        case 0: in = g_amg + 40; out = g_mg0; break;
        case 1: in = g_mg0;      out = g_mg1; break;
        case 2: in = g_mg1;      out = g_mg0; break;
        case 3: in = g_mg0;      out = g_mg1; break;
        default: in = g_mg1;     out = dout;  break;
    }
    const int n_out = 2 * ((16384 << lvl) + 1) - 1;
    const int* nbr8 = nbrs + lvl * 8;
    const float* band = g_amg + 8 * (4 - lvl);

    int p = blockIdx.x * blockDim.x + threadIdx.x;
    if (p >= n_out) return;
    float v;
    if (p & 1) {
        int h = p >> 1;
        v = 0.5f * (in[h] + in[h + 1]);
#pragma unroll
        for (int j = 0; j < 8; j++)
            if (p == nbr8[j]) v = band[j];
    } else {
        v = in[p >> 1];
    }
    out[p] = v;
}

// ---------------------------------------------------------------------------
// Launch
// ---------------------------------------------------------------------------
extern "C" void kernel_launch(void* const* d_in, const int* in_sizes, int n_in,
                              void* d_out, int out_size) {
    const float *xs, *w0, *b0, *w1, *b1, *w2, *b2, *w3, *b3, *w4, *b4;
    const int* nbrs;

    if (n_in >= 2 && in_sizes[1] == 40) {
        xs   = (const float*)d_in[0];
        nbrs = (const int*)d_in[1];
        w0 = (const float*)d_in[4];  b0 = (const float*)d_in[5];
        w1 = (const float*)d_in[6];  b1 = (const float*)d_in[7];
        w2 = (const float*)d_in[8];  b2 = (const float*)d_in[9];
        w3 = (const float*)d_in[10]; b3 = (const float*)d_in[11];
        w4 = (const float*)d_in[12]; b4 = (const float*)d_in[13];
    } else {
        xs   = (const float*)d_in[0];
        w0 = (const float*)d_in[1];  b0 = (const float*)d_in[2];
        w1 = (const float*)d_in[3];  b1 = (const float*)d_in[4];
        w2 = (const float*)d_in[5];  b2 = (const float*)d_in[6];
        w3 = (const float*)d_in[7];  b3 = (const float*)d_in[8];
        w4 = (const float*)d_in[9];  b4 = (const float*)d_in[10];
        nbrs = (const int*)d_in[11];
    }

    void* p_wh;
    cudaGetSymbolAddress(&p_wh, g_wh);
    __half* wh0 = (__half*)p_wh;
    __half* wh1 = wh0 + (size_t)HID * HID;
    __half* wh2 = wh1 + (size_t)HID * HID;

    cudaFuncSetAttribute(gemm_f16_kernel,
                         cudaFuncAttributeMaxDynamicSharedMemorySize, SMEM_BYTES);

    // Fused weight transpose + fp16 convert (all 3 layers, one launch)
    {
        dim3 gr(HID / 32, HID / 32, 3), bl(32, 8);
        transpose_half3<<<gr, bl>>>(w1, w2, w3, wh0);
    }

    // Layer 0 -> g_h0 (fp16)
    layer0_kernel<<<M_PAD / L0_ROWS, 256>>>(xs, w0, b0);

    // Three hidden GEMMs (fp16 tensor cores, fused bias+relu)
    dim3 grid(HID / BN, M_PAD / BM);  // (8, 129)
    gemm_f16_kernel<<<grid, 256, SMEM_BYTES>>>(wh0, b1, 0); // h0 -> h1
    gemm_f16_kernel<<<grid, 256, SMEM_BYTES>>>(wh1, b2, 1); // h1 -> h0
    gemm_f16_kernel<<<grid, 256, SMEM_BYTES>>>(wh2, b3, 0); // h0 -> h1

    // Final GEMV -> g_amg
    gemv_kernel<<<(M_ROWS * 32 + 255) / 256, 256>>>(w4, b4);

    // Multigrid reconstruction
    for (int lvl = 0; lvl < K_LEV; lvl++) {
        int n_out_l = (16384 << (lvl + 1)) + 1;
        mg_kernel<<<(n_out_l + 255) / 256, 256>>>(lvl, nbrs, (float*)d_out);
    }
    (void)out_size;
}